// round 3
// baseline (speedup 1.0000x reference)
#include <cuda_runtime.h>
#include <math.h>

#define Bn 4
#define GLn 4
#define Nn 1024
#define CSn 32
#define CNn 16
#define NAn 16
#define Sn 512
#define Rn 128     // GL*CS
#define K1n 512    // GL*GF
#define IKn 128    // CS*GL
#define JUn 512    // CN*CS

// -------- scratch (device globals; no allocations anywhere) --------
__device__ float g_u[Bn*Rn*Nn];        // primary caps pre-squash, [b][r=128][n=1024]
__device__ float g_msqp[Bn*GLn*16];    // squash-norm partials per (b,g,nblk)
__device__ float g_WgT[IKn*JUn];       // permuted Wg: [ik=128][ju=512]
__device__ float g_apart[Bn*32*512];   // agreement partials [b][mblk][i*16+j]
__device__ float g_blog[Bn*CSn*CNn];   // routing logits (fold of iter-0 partials)
__device__ float g_gpart[Bn*32*JUn];   // column-sum partials of final v
__device__ float g_va[Bn*NAn*CSn];     // aspect routing output

// ---------------- Wg permute: WgT[(k*32+i)*512 + j*32+u] = Wg[((i*16+j)*32+u)*4+k] ----------------
__global__ void k_permW(const float* __restrict__ Wg){
    int idx = blockIdx.x*256 + threadIdx.x;
    if (idx < IKn*JUn){
        int ik = idx >> 9, ju = idx & 511;
        int k = ik >> 5, i = ik & 31, j = ju >> 5, u = ju & 31;
        g_WgT[idx] = Wg[((i*CNn + j)*CSn + u)*GLn + k];
    }
}

// ---------------- primary caps GEMM + squash-norm partials ----------------
__global__ __launch_bounds__(256) void k_primary(const float* __restrict__ Wp,
                                                 const float* __restrict__ bp,
                                                 const float* __restrict__ X){
    __shared__ float shA[16][65];
    __shared__ float shB[16][65];
    __shared__ float red[256];
    int b = blockIdx.z;
    int m0 = blockIdx.y*64, n0 = blockIdx.x*64;
    const float* Xb = X + (size_t)b*K1n*Nn;
    int tid = threadIdx.x;
    int tx = tid & 15, ty = tid >> 4;
    float acc[4][4] = {};
    for (int k0 = 0; k0 < K1n; k0 += 16){
        for (int e = tid; e < 64*16; e += 256){
            int m = e >> 4, k = e & 15;
            shA[k][m] = Wp[(m0+m)*K1n + k0 + k];
        }
        for (int e = tid; e < 16*64; e += 256){
            int k = e >> 6, n = e & 63;
            shB[k][n] = Xb[(size_t)(k0+k)*Nn + n0 + n];
        }
        __syncthreads();
        #pragma unroll
        for (int kk = 0; kk < 16; kk++){
            float a[4], c[4];
            #pragma unroll
            for (int i = 0; i < 4; i++) a[i] = shA[kk][ty*4+i];
            #pragma unroll
            for (int j = 0; j < 4; j++) c[j] = shB[kk][tx*4+j];
            #pragma unroll
            for (int i = 0; i < 4; i++)
                #pragma unroll
                for (int j = 0; j < 4; j++)
                    acc[i][j] += a[i]*c[j];
        }
        __syncthreads();
    }
    float ssq = 0.f;
    #pragma unroll
    for (int i = 0; i < 4; i++){
        int m = m0 + ty*4 + i;
        float bias = bp[m];
        #pragma unroll
        for (int j = 0; j < 4; j++){
            float v = acc[i][j] + bias;
            g_u[(size_t)b*Rn*Nn + (size_t)m*Nn + n0 + tx*4 + j] = v;
            ssq += v*v;
        }
    }
    red[tid] = ssq; __syncthreads();
    int half = tid >> 7, lid = tid & 127;
    for (int off = 64; off; off >>= 1){
        if (lid < off) red[half*128 + lid] += red[half*128 + lid + off];
        __syncthreads();
    }
    if (lid == 0)
        g_msqp[(b*GLn + (m0 >> 5) + half)*16 + blockIdx.x] = red[half*128];
}

// ---------------- fully-fused routing iteration ----------------
// block: 32 m rows x full 512 ju. Computes s (c-weighted GEMM), squash (j local),
// then either agreement partials (iters 0,1) or final-v column sums (iter 2).
// Logit fold from the previous iteration's partials happens in the preamble.
__global__ __launch_bounds__(256) void k_route_fused(int iter){
    __shared__ float shU[IKn*33];      // full scaled-U tile [ik][m], pad 33
    __shared__ float buf[4352];        // GEMM B slab (8x512) / fold / Wc(128x33) / stages
    __shared__ float Vc[32*33];        // v column slab [m][u]
    __shared__ float c_sh[CSn][CNn];
    __shared__ float sc_sh;
    int b = blockIdx.y;
    int m0 = blockIdx.x*32;
    int tid = threadIdx.x;
    int tx = tid & 31, ty = tid >> 5;     // tx = lane = u (or i), ty = warp = m-group

    if (tid == 0){
        int grp = m0 >> 8;
        float s = 0.f;
        #pragma unroll
        for (int t = 0; t < 16; t++) s += g_msqp[(b*GLn + grp)*16 + t];
        sc_sh = sqrtf(s)/(1.f + s);
    }
    // fold previous agreement partials into logits (redundantly per block)
    if (iter >= 1){
        for (int e = tid; e < 512; e += 256){
            float s = (iter == 2) ? g_blog[b*512 + e] : 0.f;
            for (int t = 0; t < 32; t++) s += g_apart[((size_t)b*32 + t)*512 + e];
            buf[e] = s;
        }
    }
    __syncthreads();
    if (iter == 1 && blockIdx.x == 0)
        for (int e = tid; e < 512; e += 256) g_blog[b*512 + e] = buf[e];
    if (iter >= 1 && tid < 32){
        int i = tid;
        float row[CNn], mx = -1e30f;
        #pragma unroll
        for (int j = 0; j < CNn; j++){ row[j] = buf[i*16 + j]; mx = fmaxf(mx, row[j]); }
        float sum = 0.f;
        #pragma unroll
        for (int j = 0; j < CNn; j++){ row[j] = expf(row[j]-mx); sum += row[j]; }
        float inv = 1.f/sum;
        #pragma unroll
        for (int j = 0; j < CNn; j++) c_sh[i][j] = row[j]*inv;
    }
    float sc = sc_sh;
    // load full scaled U tile once: shU[ik][m]
    {
        const float* U = g_u + (size_t)b*Nn*IKn + (size_t)m0*IKn;
        for (int e = tid; e < 32*IKn; e += 256){
            int m = e >> 7, k = e & 127;
            shU[k*33 + m] = U[(size_t)m*IKn + k]*sc;
        }
    }
    __syncthreads();

    // ---- c-weighted s GEMM: acc[mm][c], col = c*32+tx ----
    float acc[4][16] = {};
    const bool unif = (iter == 0);
    for (int k0 = 0; k0 < IKn; k0 += 8){
        for (int e = tid; e < 4096; e += 256){
            int kk = e >> 9, n = e & 511;
            float w = g_WgT[(size_t)(k0+kk)*JUn + n];
            buf[e] = unif ? w*0.0625f : w*c_sh[(k0+kk) & 31][n >> 5];
        }
        __syncthreads();
        #pragma unroll
        for (int kk = 0; kk < 8; kk++){
            float a[4];
            #pragma unroll
            for (int mm = 0; mm < 4; mm++) a[mm] = shU[(k0+kk)*33 + ty*4 + mm];
            #pragma unroll
            for (int c = 0; c < 16; c++){
                float bb = buf[kk*512 + c*32 + tx];
                #pragma unroll
                for (int mm = 0; mm < 4; mm++)
                    acc[mm][c] += a[mm]*bb;
            }
        }
        __syncthreads();
    }

    // ---- squash over j (thread-local) ----
    float fac[4];
    #pragma unroll
    for (int mm = 0; mm < 4; mm++){
        float msq = 0.f;
        #pragma unroll
        for (int c = 0; c < 16; c++) msq += acc[mm][c]*acc[mm][c];
        fac[mm] = sqrtf(msq)/(1.f + msq);
    }

    if (iter < 2){
        // v in registers
        #pragma unroll
        for (int mm = 0; mm < 4; mm++)
            #pragma unroll
            for (int c = 0; c < 16; c++) acc[mm][c] *= fac[mm];
        // ---- fused agreement: a[i=tx][c] partial over this block's 32 m ----
        float a_acc[16];
        #pragma unroll
        for (int c = 0; c < 16; c++) a_acc[c] = 0.f;
        for (int c = 0; c < 16; c++){
            // stage v column slab and WgT column slab
            #pragma unroll
            for (int mm = 0; mm < 4; mm++) Vc[(ty*4+mm)*33 + tx] = acc[mm][c];
            for (int e = tid; e < 4096; e += 256){
                int ik = e >> 5, u = e & 31;
                buf[ik*33 + u] = g_WgT[(size_t)ik*JUn + c*32 + u];
            }
            __syncthreads();
            // E[mm][k] = sum_u Wc[k*32+tx][u] * v[m][u]
            float E[4][4] = {};
            #pragma unroll 4
            for (int u = 0; u < 32; u++){
                float w0 = buf[(0*32+tx)*33 + u];
                float w1 = buf[(1*32+tx)*33 + u];
                float w2 = buf[(2*32+tx)*33 + u];
                float w3 = buf[(3*32+tx)*33 + u];
                #pragma unroll
                for (int mm = 0; mm < 4; mm++){
                    float vv = Vc[(ty*4+mm)*33 + u];
                    E[mm][0] += vv*w0;
                    E[mm][1] += vv*w1;
                    E[mm][2] += vv*w2;
                    E[mm][3] += vv*w3;
                }
            }
            // d-step: a += scU[m, k*32+tx] * E[mm][k]
            float ac = 0.f;
            #pragma unroll
            for (int k = 0; k < 4; k++)
                #pragma unroll
                for (int mm = 0; mm < 4; mm++)
                    ac += shU[(k*32+tx)*33 + ty*4 + mm]*E[mm][k];
            a_acc[c] = ac;
            __syncthreads();
        }
        // reduce over warps (ty), write partials
        const float invM = 1.f/1024.f;
        #pragma unroll
        for (int c = 0; c < 16; c++) buf[ty*512 + tx*16 + c] = a_acc[c]*invM;
        __syncthreads();
        for (int e = tid; e < 512; e += 256){
            float s = 0.f;
            #pragma unroll
            for (int w = 0; w < 8; w++) s += buf[w*512 + e];
            g_apart[((size_t)b*32 + blockIdx.x)*512 + e] = s;
        }
    } else {
        // final iter: column sums of v for g = mean_m v
        float cs[16];
        #pragma unroll
        for (int c = 0; c < 16; c++){
            float s = 0.f;
            #pragma unroll
            for (int mm = 0; mm < 4; mm++) s += acc[mm][c]*fac[mm];
            cs[c] = s;
        }
        __syncthreads();
        #pragma unroll
        for (int c = 0; c < 16; c++) buf[ty*512 + c*32 + tx] = cs[c];
        __syncthreads();
        for (int col = tid; col < 512; col += 256){
            float s = 0.f;
            #pragma unroll
            for (int w = 0; w < 8; w++) s += buf[w*512 + col];
            g_gpart[((size_t)b*32 + blockIdx.x)*JUn + col] = s;
        }
    }
}

// ---------------- aspect stage (hidden cancels; M collapses to 1) ----------------
__global__ __launch_bounds__(256) void k_aspect(const float* __restrict__ Wa,
                                                const float* __restrict__ Ws){
    __shared__ float g[CNn][CSn];
    __shared__ float cond[CNn][CSn];
    __shared__ float uh[CNn][NAn][CSn];
    __shared__ float b2[CNn][NAn];
    __shared__ float c2[CNn][NAn];
    __shared__ float s2[NAn][CSn];
    __shared__ float v2[NAn][CSn];
    __shared__ float facu[CSn];
    __shared__ float score[CNn];
    int b = blockIdx.x, tid = threadIdx.x;
    const float invN = 1.f/1024.f;
    for (int e = tid; e < JUn; e += 256){
        float t = 0.f;
        #pragma unroll
        for (int s = 0; s < 32; s++) t += g_gpart[((size_t)b*32 + s)*JUn + e];
        g[e>>5][e&31] = t*invN;
    }
    __syncthreads();
    if (tid == 0){
        float gw[CNn], mx = -1e30f;
        for (int i = 0; i < CNn; i++){
            float s = 0.f;
            for (int u = 0; u < CSn; u++) s += g[i][u]*Wa[u];
            gw[i] = s; mx = fmaxf(mx, s);
        }
        float sum = 0.f;
        for (int i = 0; i < CNn; i++){ gw[i] = expf(gw[i]-mx); sum += gw[i]; }
        float inv = 1.f/sum;
        for (int i = 0; i < CNn; i++) score[i] = gw[i]*inv;
    }
    __syncthreads();
    for (int e = tid; e < JUn; e += 256)
        cond[e>>5][e&31] = g[e>>5][e&31]*score[e>>5];
    if (tid < 256){ int i = tid >> 4, j = tid & 15; b2[i][j] = 0.f; }
    __syncthreads();
    for (int e = tid; e < CNn*NAn*CSn; e += 256){
        int i = e >> 9, j = (e >> 5) & 15, u = e & 31;
        float s = 0.f;
        const float* wrow = Ws + ((size_t)((i*NAn+j)*CSn+u))*CSn;
        #pragma unroll
        for (int k = 0; k < CSn; k++) s += wrow[k]*cond[i][k];
        uh[i][j][u] = s;
    }
    __syncthreads();
    for (int it = 0; it < 3; it++){
        if (tid < CNn){
            int i = tid;
            float mx = -1e30f;
            #pragma unroll
            for (int j = 0; j < NAn; j++) mx = fmaxf(mx, b2[i][j]);
            float sum = 0.f, r[NAn];
            #pragma unroll
            for (int j = 0; j < NAn; j++){ r[j] = expf(b2[i][j]-mx); sum += r[j]; }
            float inv = 1.f/sum;
            #pragma unroll
            for (int j = 0; j < NAn; j++) c2[i][j] = r[j]*inv;
        }
        __syncthreads();
        for (int e = tid; e < NAn*CSn; e += 256){
            int j = e >> 5, u = e & 31;
            float s = 0.f;
            #pragma unroll
            for (int i = 0; i < CNn; i++) s += c2[i][j]*uh[i][j][u];
            s2[j][u] = s;
        }
        __syncthreads();
        if (tid < CSn){
            int u = tid; float ms = 0.f;
            #pragma unroll
            for (int j = 0; j < NAn; j++) ms += s2[j][u]*s2[j][u];
            facu[u] = sqrtf(ms)/(1.f+ms);
        }
        __syncthreads();
        for (int e = tid; e < NAn*CSn; e += 256){
            int j = e >> 5, u = e & 31;
            v2[j][u] = s2[j][u]*facu[u];
        }
        __syncthreads();
        if (it < 2){
            if (tid < 256){
                int i = tid >> 4, j = tid & 15;
                float a = 0.f;
                #pragma unroll
                for (int u = 0; u < CSn; u++) a += uh[i][j][u]*v2[j][u];
                b2[i][j] += a;
            }
            __syncthreads();
        }
    }
    for (int e = tid; e < NAn*CSn; e += 256)
        g_va[b*NAn*CSn + e] = v2[e>>5][e&31];
}

// ---------------- broadcast final v to all S rows ----------------
__global__ __launch_bounds__(256) void k_broadcast(float* __restrict__ out){
    int idx = blockIdx.x*blockDim.x + threadIdx.x;
    if (idx < Bn*Sn*NAn*CSn){
        int b = idx >> 18;
        out[idx] = g_va[b*NAn*CSn + (idx & 511)];
    }
}

extern "C" void kernel_launch(void* const* d_in, const int* in_sizes, int n_in,
                              void* d_out, int out_size){
    (void)in_sizes; (void)n_in; (void)out_size;
    const float* ge = (const float*)d_in[0];
    // d_in[1] = hidden: cancels exactly in the softmax over capsules; never read.
    const float* Wp = (const float*)d_in[2];
    const float* bp = (const float*)d_in[3];
    const float* Wg = (const float*)d_in[4];
    const float* Wa = (const float*)d_in[5];
    const float* Ws = (const float*)d_in[6];
    float* out = (float*)d_out;

    k_permW<<<256, 256>>>(Wg);
    k_primary<<<dim3(16, 2, Bn), 256>>>(Wp, bp, ge);
    for (int t = 0; t < 3; t++)
        k_route_fused<<<dim3(32, Bn), 256>>>(t);
    k_aspect<<<Bn, 256>>>(Wa, Ws);
    k_broadcast<<<(Bn*Sn*NAn*CSn + 255)/256, 256>>>(out);
}

// round 4
// speedup vs baseline: 1.1506x; 1.1506x over previous
#include <cuda_runtime.h>
#include <math.h>

#define Bn 4
#define GLn 4
#define Nn 1024
#define CSn 32
#define CNn 16
#define NAn 16
#define Sn 512
#define Rn 128     // GL*CS
#define K1n 512    // GL*GF
#define IKn 128    // CS*GL
#define JUn 512    // CN*CS

// -------- scratch (device globals; no allocations anywhere) --------
__device__ float g_u[Bn*Rn*Nn];          // primary caps pre-squash, [b][r=128][n=1024]
__device__ float g_msqp[Bn*GLn*16];      // squash-norm partials per (b,g,nblk)
__device__ float g_WgT[IKn*JUn];         // permuted Wg: [ik=128][ju=512]
__device__ float g_V[Bn*Nn*JUn];         // routing v
__device__ float g_apart[Bn*16*8*64];    // agreement partials [b][msplit][jub][i*2+jg]
__device__ float g_blog[Bn*CSn*CNn];     // routing logits
__device__ float g_gpart[Bn*64*JUn];     // column-sum partials of final v
__device__ float g_va[Bn*NAn*CSn];       // aspect routing output

// ---------------- Wg permute ----------------
__global__ void k_permW(const float* __restrict__ Wg){
    int idx = blockIdx.x*256 + threadIdx.x;
    if (idx < IKn*JUn){
        int ik = idx >> 9, ju = idx & 511;
        int k = ik >> 5, i = ik & 31, j = ju >> 5, u = ju & 31;
        g_WgT[idx] = Wg[((i*CNn + j)*CSn + u)*GLn + k];
    }
}

// ---------------- primary caps GEMM + squash-norm partials ----------------
__global__ __launch_bounds__(256) void k_primary(const float* __restrict__ Wp,
                                                 const float* __restrict__ bp,
                                                 const float* __restrict__ X){
    __shared__ float shA[16][65];
    __shared__ float shB[16][65];
    __shared__ float red[256];
    int b = blockIdx.z;
    int m0 = blockIdx.y*64, n0 = blockIdx.x*64;
    const float* Xb = X + (size_t)b*K1n*Nn;
    int tid = threadIdx.x;
    int tx = tid & 15, ty = tid >> 4;
    float acc[4][4] = {};
    for (int k0 = 0; k0 < K1n; k0 += 16){
        for (int e = tid; e < 64*16; e += 256){
            int m = e >> 4, k = e & 15;
            shA[k][m] = Wp[(m0+m)*K1n + k0 + k];
        }
        for (int e = tid; e < 16*64; e += 256){
            int k = e >> 6, n = e & 63;
            shB[k][n] = Xb[(size_t)(k0+k)*Nn + n0 + n];
        }
        __syncthreads();
        #pragma unroll
        for (int kk = 0; kk < 16; kk++){
            float a[4], c[4];
            #pragma unroll
            for (int i = 0; i < 4; i++) a[i] = shA[kk][ty*4+i];
            #pragma unroll
            for (int j = 0; j < 4; j++) c[j] = shB[kk][tx*4+j];
            #pragma unroll
            for (int i = 0; i < 4; i++)
                #pragma unroll
                for (int j = 0; j < 4; j++)
                    acc[i][j] += a[i]*c[j];
        }
        __syncthreads();
    }
    float ssq = 0.f;
    #pragma unroll
    for (int i = 0; i < 4; i++){
        int m = m0 + ty*4 + i;
        float bias = bp[m];
        #pragma unroll
        for (int j = 0; j < 4; j++){
            float v = acc[i][j] + bias;
            g_u[(size_t)b*Rn*Nn + (size_t)m*Nn + n0 + tx*4 + j] = v;
            ssq += v*v;
        }
    }
    red[tid] = ssq; __syncthreads();
    int half = tid >> 7, lid = tid & 127;
    for (int off = 64; off; off >>= 1){
        if (lid < off) red[half*128 + lid] += red[half*128 + lid + off];
        __syncthreads();
    }
    if (lid == 0)
        g_msqp[(b*GLn + (m0 >> 5) + half)*16 + blockIdx.x] = red[half*128];
}

// ---------------- routing-s GEMM + squash (16 m rows x full 512 ju) ----------------
// grid (64 m-blocks, Bn); thread: tx=u lane, ty=warp; m = m0+ty*2+mm, col = c*32+tx.
__global__ __launch_bounds__(256,3) void k_route(int iter){
    __shared__ float shU[128][18];     // [k][m] scaled U tile
    __shared__ float bufB[8*512];      // B slab [kk][n]; reused for gpart staging
    __shared__ float c_sh[32][16];
    __shared__ float fb[512];
    __shared__ float sc_sh;
    int b = blockIdx.y;
    int m0 = blockIdx.x*16;
    int tid = threadIdx.x;
    int tx = tid & 31, ty = tid >> 5;

    if (tid == 0){
        int grp = m0 >> 8;
        float s = 0.f;
        #pragma unroll
        for (int t = 0; t < 16; t++) s += g_msqp[(b*GLn + grp)*16 + t];
        sc_sh = sqrtf(s)/(1.f + s);
    }
    if (iter >= 1){
        // fold agreement partials (16 per logit) into fb
        for (int e = tid; e < 512; e += 256){
            float s = (iter == 2) ? g_blog[b*512 + e] : 0.f;
            int i = e >> 4, j = e & 15;
            #pragma unroll
            for (int ms = 0; ms < 16; ms++)
                s += g_apart[((b*16 + ms)*8 + (j >> 1))*64 + i*2 + (j & 1)];
            fb[e] = s;
        }
    }
    __syncthreads();
    float sc = sc_sh;
    if (iter == 1 && blockIdx.x == 0)
        for (int e = tid; e < 512; e += 256) g_blog[b*512 + e] = fb[e];
    if (iter >= 1 && tid < 32){
        int i = tid;
        float row[CNn], mx = -1e30f;
        #pragma unroll
        for (int j = 0; j < CNn; j++){ row[j] = fb[i*16 + j]; mx = fmaxf(mx, row[j]); }
        float sum = 0.f;
        #pragma unroll
        for (int j = 0; j < CNn; j++){ row[j] = expf(row[j]-mx); sum += row[j]; }
        float inv = 1.f/sum;
        #pragma unroll
        for (int j = 0; j < CNn; j++) c_sh[i][j] = row[j]*inv;
    }
    {
        const float* U = g_u + (size_t)b*Nn*IKn + (size_t)m0*IKn;
        for (int e = tid; e < 16*128; e += 256){
            int m = e >> 7, k = e & 127;
            shU[k][m] = U[(size_t)m*IKn + k]*sc;
        }
    }
    __syncthreads();

    float acc[2][16] = {};
    const bool unif = (iter == 0);
    for (int k0 = 0; k0 < IKn; k0 += 8){
        for (int e = tid; e < 4096; e += 256){
            int kk = e >> 9, n = e & 511;
            float w = g_WgT[(size_t)(k0+kk)*JUn + n];
            bufB[e] = unif ? w*0.0625f : w*c_sh[(k0+kk) & 31][n >> 5];
        }
        __syncthreads();
        #pragma unroll
        for (int kk = 0; kk < 8; kk++){
            float a0 = shU[k0+kk][ty*2];
            float a1 = shU[k0+kk][ty*2+1];
            #pragma unroll
            for (int c = 0; c < 16; c++){
                float bb = bufB[kk*512 + c*32 + tx];
                acc[0][c] += a0*bb;
                acc[1][c] += a1*bb;
            }
        }
        __syncthreads();
    }

    // squash over j (thread-local: j == c)
    float fac[2];
    #pragma unroll
    for (int mm = 0; mm < 2; mm++){
        float msq = 0.f;
        #pragma unroll
        for (int c = 0; c < 16; c++) msq += acc[mm][c]*acc[mm][c];
        fac[mm] = sqrtf(msq)/(1.f + msq);
    }
    if (iter < 2){
        float* Vp = g_V + (size_t)b*Nn*JUn;
        #pragma unroll
        for (int mm = 0; mm < 2; mm++){
            size_t rb = (size_t)(m0 + ty*2 + mm)*JUn;
            #pragma unroll
            for (int c = 0; c < 16; c++)
                Vp[rb + c*32 + tx] = acc[mm][c]*fac[mm];
        }
    } else {
        float cs[16];
        #pragma unroll
        for (int c = 0; c < 16; c++)
            cs[c] = acc[0][c]*fac[0] + acc[1][c]*fac[1];
        __syncthreads();
        #pragma unroll
        for (int c = 0; c < 16; c++) bufB[ty*512 + c*32 + tx] = cs[c];
        __syncthreads();
        for (int col = tid; col < 512; col += 256){
            float s = 0.f;
            #pragma unroll
            for (int w = 0; w < 8; w++) s += bufB[w*512 + col];
            g_gpart[((size_t)b*64 + blockIdx.x)*JUn + col] = s;
        }
    }
}

// ---------------- T GEMM (128 ik x 64 ju x 64 m) + fused agreement partials ----------------
// grid (8 nblk, 16 msplit, Bn)
__global__ __launch_bounds__(256) void k_T_agree(){
    __shared__ float shU[16][128];
    __shared__ float shV[16][64];
    __shared__ float stage[16][16][8];
    __shared__ float sc_sh;
    int b = blockIdx.z, nblk = blockIdx.x, msb = blockIdx.y;
    int n0 = nblk*64, mbase = msb*64;
    int tid = threadIdx.x;
    int rg = tid >> 4, cg = tid & 15;
    if (tid == 0){
        int grp = mbase >> 8;
        float s = 0.f;
        #pragma unroll
        for (int t = 0; t < 16; t++) s += g_msqp[(b*GLn + grp)*16 + t];
        sc_sh = sqrtf(s)/(1.f + s);
    }
    __syncthreads();
    float sc = sc_sh;
    const float* U = g_u + (size_t)b*Nn*IKn;
    const float* V = g_V + (size_t)b*Nn*JUn;
    float acc[8][4] = {};
    for (int mc = 0; mc < 64; mc += 16){
        int mm0 = mbase + mc;
        for (int e = tid; e < 2048; e += 256){
            int m = e >> 7, p = e & 127;
            shU[m][p] = U[(size_t)(mm0+m)*IKn + p]*sc;
        }
        for (int e = tid; e < 1024; e += 256){
            int m = e >> 6, n = e & 63;
            shV[m][n] = V[(size_t)(mm0+m)*JUn + n0 + n];
        }
        __syncthreads();
        #pragma unroll
        for (int kk = 0; kk < 16; kk++){
            float a[8];
            #pragma unroll
            for (int i = 0; i < 8; i++) a[i] = shU[kk][rg*8+i];
            float4 c4 = *(float4*)&shV[kk][cg*4];
            #pragma unroll
            for (int i = 0; i < 8; i++){
                acc[i][0] += a[i]*c4.x;
                acc[i][1] += a[i]*c4.y;
                acc[i][2] += a[i]*c4.z;
                acc[i][3] += a[i]*c4.w;
            }
        }
        __syncthreads();
    }
    // agreement: dot T tile with WgT
    const float invM = 1.f/1024.f;
    #pragma unroll
    for (int i8 = 0; i8 < 8; i8++){
        int row = rg*8 + i8;
        float4 w4 = *(const float4*)(g_WgT + (size_t)row*JUn + n0 + cg*4);
        float s = acc[i8][0]*w4.x + acc[i8][1]*w4.y + acc[i8][2]*w4.z + acc[i8][3]*w4.w;
        stage[rg][cg][i8] = s*invM;
    }
    __syncthreads();
    if (tid < 64){
        int i = tid >> 1, jg = tid & 1;
        float s = 0.f;
        #pragma unroll
        for (int r4 = 0; r4 < 4; r4++){
            int rgp = (i >> 3) + r4*4;
            #pragma unroll
            for (int c8 = 0; c8 < 8; c8++)
                s += stage[rgp][jg*8 + c8][i & 7];
        }
        g_apart[((b*16 + msb)*8 + nblk)*64 + i*2 + jg] = s;
    }
}

// ---------------- aspect stage (hidden cancels; M collapses to 1) ----------------
__global__ __launch_bounds__(256) void k_aspect(const float* __restrict__ Wa,
                                                const float* __restrict__ Ws){
    __shared__ float g[CNn][CSn];
    __shared__ float cond[CNn][CSn];
    __shared__ float uh[CNn][NAn][CSn];
    __shared__ float b2[CNn][NAn];
    __shared__ float c2[CNn][NAn];
    __shared__ float s2[NAn][CSn];
    __shared__ float v2[NAn][CSn];
    __shared__ float facu[CSn];
    __shared__ float score[CNn];
    int b = blockIdx.x, tid = threadIdx.x;
    const float invN = 1.f/1024.f;
    for (int e = tid; e < JUn; e += 256){
        float t = 0.f;
        #pragma unroll
        for (int s = 0; s < 64; s++) t += g_gpart[((size_t)b*64 + s)*JUn + e];
        g[e>>5][e&31] = t*invN;
    }
    __syncthreads();
    if (tid == 0){
        float gw[CNn], mx = -1e30f;
        for (int i = 0; i < CNn; i++){
            float s = 0.f;
            for (int u = 0; u < CSn; u++) s += g[i][u]*Wa[u];
            gw[i] = s; mx = fmaxf(mx, s);
        }
        float sum = 0.f;
        for (int i = 0; i < CNn; i++){ gw[i] = expf(gw[i]-mx); sum += gw[i]; }
        float inv = 1.f/sum;
        for (int i = 0; i < CNn; i++) score[i] = gw[i]*inv;
    }
    __syncthreads();
    for (int e = tid; e < JUn; e += 256)
        cond[e>>5][e&31] = g[e>>5][e&31]*score[e>>5];
    if (tid < 256){ int i = tid >> 4, j = tid & 15; b2[i][j] = 0.f; }
    __syncthreads();
    for (int e = tid; e < CNn*NAn*CSn; e += 256){
        int i = e >> 9, j = (e >> 5) & 15, u = e & 31;
        float s = 0.f;
        const float* wrow = Ws + ((size_t)((i*NAn+j)*CSn+u))*CSn;
        #pragma unroll
        for (int k = 0; k < CSn; k++) s += wrow[k]*cond[i][k];
        uh[i][j][u] = s;
    }
    __syncthreads();
    for (int it = 0; it < 3; it++){
        if (tid < CNn){
            int i = tid;
            float mx = -1e30f;
            #pragma unroll
            for (int j = 0; j < NAn; j++) mx = fmaxf(mx, b2[i][j]);
            float sum = 0.f, r[NAn];
            #pragma unroll
            for (int j = 0; j < NAn; j++){ r[j] = expf(b2[i][j]-mx); sum += r[j]; }
            float inv = 1.f/sum;
            #pragma unroll
            for (int j = 0; j < NAn; j++) c2[i][j] = r[j]*inv;
        }
        __syncthreads();
        for (int e = tid; e < NAn*CSn; e += 256){
            int j = e >> 5, u = e & 31;
            float s = 0.f;
            #pragma unroll
            for (int i = 0; i < CNn; i++) s += c2[i][j]*uh[i][j][u];
            s2[j][u] = s;
        }
        __syncthreads();
        if (tid < CSn){
            int u = tid; float ms = 0.f;
            #pragma unroll
            for (int j = 0; j < NAn; j++) ms += s2[j][u]*s2[j][u];
            facu[u] = sqrtf(ms)/(1.f+ms);
        }
        __syncthreads();
        for (int e = tid; e < NAn*CSn; e += 256){
            int j = e >> 5, u = e & 31;
            v2[j][u] = s2[j][u]*facu[u];
        }
        __syncthreads();
        if (it < 2){
            if (tid < 256){
                int i = tid >> 4, j = tid & 15;
                float a = 0.f;
                #pragma unroll
                for (int u = 0; u < CSn; u++) a += uh[i][j][u]*v2[j][u];
                b2[i][j] += a;
            }
            __syncthreads();
        }
    }
    for (int e = tid; e < NAn*CSn; e += 256)
        g_va[b*NAn*CSn + e] = v2[e>>5][e&31];
}

// ---------------- broadcast final v to all S rows ----------------
__global__ __launch_bounds__(256) void k_broadcast(float* __restrict__ out){
    int idx = blockIdx.x*blockDim.x + threadIdx.x;
    if (idx < Bn*Sn*NAn*CSn){
        int b = idx >> 18;
        out[idx] = g_va[b*NAn*CSn + (idx & 511)];
    }
}

extern "C" void kernel_launch(void* const* d_in, const int* in_sizes, int n_in,
                              void* d_out, int out_size){
    (void)in_sizes; (void)n_in; (void)out_size;
    const float* ge = (const float*)d_in[0];
    // d_in[1] = hidden: cancels exactly in the softmax over capsules; never read.
    const float* Wp = (const float*)d_in[2];
    const float* bp = (const float*)d_in[3];
    const float* Wg = (const float*)d_in[4];
    const float* Wa = (const float*)d_in[5];
    const float* Ws = (const float*)d_in[6];
    float* out = (float*)d_out;

    k_permW<<<256, 256>>>(Wg);
    k_primary<<<dim3(16, 2, Bn), 256>>>(Wp, bp, ge);
    for (int t = 0; t < 3; t++){
        k_route<<<dim3(64, Bn), 256>>>(t);
        if (t < 2)
            k_T_agree<<<dim3(8, 16, Bn), 256>>>();
    }
    k_aspect<<<Bn, 256>>>(Wa, Ws);
    k_broadcast<<<(Bn*Sn*NAn*CSn + 255)/256, 256>>>(out);
}

// round 5
// speedup vs baseline: 1.5904x; 1.3823x over previous
#include <cuda_runtime.h>
#include <math.h>

#define Bn 4
#define GLn 4
#define Nn 1024
#define CSn 32
#define CNn 16
#define NAn 16
#define Sn 512
#define Rn 128     // GL*CS
#define K1n 512    // GL*GF
#define IKn 128    // CS*GL
#define JUn 512    // CN*CS

// -------- scratch (device globals; no allocations anywhere) --------
__device__ float g_u[Bn*Rn*Nn];          // primary caps pre-squash, [b][m=128][n=1024]
__device__ float g_msqp[Bn*GLn*8];       // squash-norm partials per (b,g,nblk)
__device__ float g_WgT[IKn*JUn];         // permuted Wg: [ik=128][ju=512]
__device__ float g_V[Bn*Nn*JUn];         // routing v
__device__ float g_apart[Bn*16*8*64];    // agreement partials [b][msplit][jub][i*2+jg]
__device__ float g_blog[Bn*CSn*CNn];     // routing logits
__device__ float g_gpart[Bn*64*JUn];     // column-sum partials of final v
__device__ float g_va[Bn*NAn*CSn];       // aspect routing output

// ---------------- tf32 helpers ----------------
__device__ __forceinline__ unsigned f2tf(float f){
    unsigned r; asm("cvt.rna.tf32.f32 %0, %1;" : "=r"(r) : "f"(f)); return r;
}
__device__ __forceinline__ void mma_tf32(float* d, unsigned a0, unsigned a1,
                                         unsigned a2, unsigned a3,
                                         unsigned b0, unsigned b1){
    asm volatile(
        "mma.sync.aligned.m16n8k8.row.col.f32.tf32.tf32.f32 "
        "{%0,%1,%2,%3}, {%4,%5,%6,%7}, {%8,%9}, {%0,%1,%2,%3};"
        : "+f"(d[0]), "+f"(d[1]), "+f"(d[2]), "+f"(d[3])
        : "r"(a0), "r"(a1), "r"(a2), "r"(a3), "r"(b0), "r"(b1));
}

// ---------------- Wg permute ----------------
__global__ void k_permW(const float* __restrict__ Wg){
    int idx = blockIdx.x*256 + threadIdx.x;
    if (idx < IKn*JUn){
        int ik = idx >> 9, ju = idx & 511;
        int k = ik >> 5, i = ik & 31, j = ju >> 5, u = ju & 31;
        g_WgT[idx] = Wg[((i*CNn + j)*CSn + u)*GLn + k];
    }
}

// ---------------- primary caps GEMM (tf32 mma) + squash-norm partials ----------------
// grid (8 nblk, 4 mblk, Bn); block tile 32m x 128n, k=512.
__global__ __launch_bounds__(256) void k_primary(const float* __restrict__ Wp,
                                                 const float* __restrict__ bp,
                                                 const float* __restrict__ X){
    __shared__ unsigned shA[32][20];
    __shared__ unsigned shB[16][136];
    __shared__ float red[256];
    int b = blockIdx.z;
    int m0 = blockIdx.y*32, n0 = blockIdx.x*128;
    const float* Xb = X + (size_t)b*K1n*Nn;
    int tid = threadIdx.x;
    int w = tid >> 5, lane = tid & 31, gid = lane >> 2, t4 = lane & 3;
    int wm = w >> 2, wn = w & 3;
    float d[4][4] = {};
    for (int k0 = 0; k0 < K1n; k0 += 16){
        #pragma unroll
        for (int e = tid; e < 32*16; e += 256){
            int m = e >> 4, k = e & 15;
            shA[m][k] = f2tf(Wp[(m0+m)*K1n + k0 + k]);
        }
        #pragma unroll
        for (int e = tid; e < 16*128; e += 256){
            int k = e >> 7, n = e & 127;
            shB[k][n] = f2tf(Xb[(size_t)(k0+k)*Nn + n0 + n]);
        }
        __syncthreads();
        #pragma unroll
        for (int ks = 0; ks < 2; ks++){
            unsigned a0 = shA[wm*16+gid  ][ks*8+t4  ];
            unsigned a1 = shA[wm*16+gid+8][ks*8+t4  ];
            unsigned a2 = shA[wm*16+gid  ][ks*8+t4+4];
            unsigned a3 = shA[wm*16+gid+8][ks*8+t4+4];
            #pragma unroll
            for (int nt = 0; nt < 4; nt++){
                int n = wn*32 + nt*8 + gid;
                unsigned b0 = shB[ks*8+t4  ][n];
                unsigned b1 = shB[ks*8+t4+4][n];
                mma_tf32(d[nt], a0, a1, a2, a3, b0, b1);
            }
        }
        __syncthreads();
    }
    int mA = m0 + wm*16 + gid, mB = mA + 8;
    float biasA = bp[mA], biasB = bp[mB];
    float ssq = 0.f;
    #pragma unroll
    for (int nt = 0; nt < 4; nt++){
        int n = n0 + wn*32 + nt*8 + t4*2;
        float v0 = d[nt][0] + biasA, v1 = d[nt][1] + biasA;
        float v2 = d[nt][2] + biasB, v3 = d[nt][3] + biasB;
        *(float2*)&g_u[(size_t)b*Rn*Nn + (size_t)mA*Nn + n] = make_float2(v0, v1);
        *(float2*)&g_u[(size_t)b*Rn*Nn + (size_t)mB*Nn + n] = make_float2(v2, v3);
        ssq += v0*v0 + v1*v1 + v2*v2 + v3*v3;
    }
    red[tid] = ssq; __syncthreads();
    for (int off = 128; off; off >>= 1){
        if (tid < off) red[tid] += red[tid+off];
        __syncthreads();
    }
    if (tid == 0)
        g_msqp[(b*GLn + blockIdx.y)*8 + blockIdx.x] = red[0];
}

// ---------------- routing-s GEMM (tf32 mma) + squash ----------------
// grid (64 m-blocks, Bn); block tile 16m x 512ju (full j extent), k=128.
__global__ __launch_bounds__(256) void k_route(int iter){
    __shared__ float SM[16*520];            // sbuf [16][520]; aliased below
    __shared__ float c_sh[32][16];
    __shared__ float fb[512];
    __shared__ float sc_sh;
    unsigned* shA  = (unsigned*)SM;          // [16][132] = 2112
    unsigned* bufB = (unsigned*)SM + 2112;   // [8][520]  = 4160 (ends 6272 < 8320)
    int b = blockIdx.y;
    int m0 = blockIdx.x*16;
    int tid = threadIdx.x;
    int w = tid >> 5, lane = tid & 31, gid = lane >> 2, t4 = lane & 3;

    if (tid == 0){
        int grp = m0 >> 8;
        float s = 0.f;
        #pragma unroll
        for (int t = 0; t < 8; t++) s += g_msqp[(b*GLn + grp)*8 + t];
        sc_sh = sqrtf(s)/(1.f + s);
    }
    if (iter >= 1){
        for (int e = tid; e < 512; e += 256){
            float s = (iter == 2) ? g_blog[b*512 + e] : 0.f;
            int i = e >> 4, j = e & 15;
            #pragma unroll
            for (int ms = 0; ms < 16; ms++)
                s += g_apart[((b*16 + ms)*8 + (j >> 1))*64 + i*2 + (j & 1)];
            fb[e] = s;
        }
    }
    __syncthreads();
    float sc = sc_sh;
    if (iter == 1 && blockIdx.x == 0)
        for (int e = tid; e < 512; e += 256) g_blog[b*512 + e] = fb[e];
    if (iter >= 1 && tid < 32){
        int i = tid;
        float row[CNn], mx = -1e30f;
        #pragma unroll
        for (int j = 0; j < CNn; j++){ row[j] = fb[i*16 + j]; mx = fmaxf(mx, row[j]); }
        float sum = 0.f;
        #pragma unroll
        for (int j = 0; j < CNn; j++){ row[j] = expf(row[j]-mx); sum += row[j]; }
        float inv = 1.f/sum;
        #pragma unroll
        for (int j = 0; j < CNn; j++) c_sh[i][j] = row[j]*inv;
    }
    // stage full scaled-U tile [16m][128k] as tf32
    {
        const float* U = g_u + (size_t)b*Nn*IKn + (size_t)m0*IKn;
        #pragma unroll
        for (int e = tid; e < 16*128; e += 256){
            int m = e >> 7, k = e & 127;
            shA[m*132 + k] = f2tf(U[(size_t)m*IKn + k]*sc);
        }
    }
    __syncthreads();

    float d[8][4] = {};       // warp covers cols w*64..w*64+63 (8 n-tiles)
    const bool unif = (iter == 0);
    for (int k0 = 0; k0 < IKn; k0 += 8){
        #pragma unroll
        for (int e = tid; e < 4096; e += 256){
            int kk = e >> 9, n = e & 511;
            float wv = g_WgT[(size_t)(k0+kk)*JUn + n];
            float val = unif ? wv*0.0625f : wv*c_sh[(k0+kk) & 31][n >> 5];
            bufB[kk*520 + n] = f2tf(val);
        }
        __syncthreads();
        unsigned a0 = shA[ gid   *132 + k0 + t4  ];
        unsigned a1 = shA[(gid+8)*132 + k0 + t4  ];
        unsigned a2 = shA[ gid   *132 + k0 + t4+4];
        unsigned a3 = shA[(gid+8)*132 + k0 + t4+4];
        #pragma unroll
        for (int nt = 0; nt < 8; nt++){
            int n = w*64 + nt*8 + gid;
            unsigned b0 = bufB[ t4   *520 + n];
            unsigned b1 = bufB[(t4+4)*520 + n];
            mma_tf32(d[nt], a0, a1, a2, a3, b0, b1);
        }
        __syncthreads();
    }
    // stage s into sbuf (reuses shA/bufB region; mma reads completed at last sync)
    #pragma unroll
    for (int nt = 0; nt < 8; nt++){
        int n = w*64 + nt*8 + t4*2;
        SM[ gid   *520 + n    ] = d[nt][0];
        SM[ gid   *520 + n + 1] = d[nt][1];
        SM[(gid+8)*520 + n    ] = d[nt][2];
        SM[(gid+8)*520 + n + 1] = d[nt][3];
    }
    __syncthreads();
    // squash over j (per m,u)
    if (iter < 2){
        float* Vp = g_V + (size_t)b*Nn*JUn;
        for (int e = tid; e < 512; e += 256){
            int m = e >> 5, u = e & 31;
            float msq = 0.f;
            #pragma unroll
            for (int j = 0; j < CNn; j++){
                float v = SM[m*520 + j*32 + u];
                msq += v*v;
            }
            float fac = sqrtf(msq)/(1.f + msq);
            #pragma unroll
            for (int j = 0; j < CNn; j++)
                Vp[(size_t)(m0+m)*JUn + j*32 + u] = SM[m*520 + j*32 + u]*fac;
        }
    } else {
        for (int e = tid; e < 512; e += 256){
            int m = e >> 5, u = e & 31;
            float msq = 0.f;
            #pragma unroll
            for (int j = 0; j < CNn; j++){
                float v = SM[m*520 + j*32 + u];
                msq += v*v;
            }
            float fac = sqrtf(msq)/(1.f + msq);
            #pragma unroll
            for (int j = 0; j < CNn; j++)
                SM[m*520 + j*32 + u] *= fac;
        }
        __syncthreads();
        for (int col = tid; col < 512; col += 256){
            float s = 0.f;
            #pragma unroll
            for (int m = 0; m < 16; m++) s += SM[m*520 + col];
            g_gpart[((size_t)b*64 + blockIdx.x)*JUn + col] = s;
        }
    }
}

// ---------------- T GEMM (tf32 mma, 128ik x 64ju x 64m) + fused agreement ----------------
// grid (8 nblk, 16 msplit, Bn); warp tile 32ik x 32ju (wik = w>>1, wju = w&1).
__global__ __launch_bounds__(256) void k_T_agree(){
    __shared__ unsigned shUT[128][20];     // [ik][m]
    __shared__ unsigned shV[16][72];       // [m][n]
    __shared__ float shAg[8][32];
    __shared__ float sc_sh;
    int b = blockIdx.z, nblk = blockIdx.x, msb = blockIdx.y;
    int n0 = nblk*64, mbase = msb*64;
    int tid = threadIdx.x;
    int w = tid >> 5, lane = tid & 31, gid = lane >> 2, t4 = lane & 3;
    int wik = w >> 1, wju = w & 1;
    if (tid == 0){
        int grp = mbase >> 8;
        float s = 0.f;
        #pragma unroll
        for (int t = 0; t < 8; t++) s += g_msqp[(b*GLn + grp)*8 + t];
        sc_sh = sqrtf(s)/(1.f + s);
    }
    __syncthreads();
    float sc = sc_sh;
    const float* U = g_u + (size_t)b*Nn*IKn;
    const float* V = g_V + (size_t)b*Nn*JUn;
    float d[2][4][4] = {};     // [mtile(ik)][ntile][4]
    for (int mc = 0; mc < 64; mc += 16){
        int mm0 = mbase + mc;
        #pragma unroll
        for (int e = tid; e < 2048; e += 256){
            int m = e >> 7, ik = e & 127;
            shUT[ik][m] = f2tf(U[(size_t)(mm0+m)*IKn + ik]*sc);
        }
        #pragma unroll
        for (int e = tid; e < 1024; e += 256){
            int m = e >> 6, n = e & 63;
            shV[m][n] = f2tf(V[(size_t)(mm0+m)*JUn + n0 + n]);
        }
        __syncthreads();
        #pragma unroll
        for (int ks = 0; ks < 2; ks++){
            unsigned bb[4][2];
            #pragma unroll
            for (int nt = 0; nt < 4; nt++){
                int n = wju*32 + nt*8 + gid;
                bb[nt][0] = shV[ks*8+t4  ][n];
                bb[nt][1] = shV[ks*8+t4+4][n];
            }
            #pragma unroll
            for (int mt = 0; mt < 2; mt++){
                int r = wik*32 + mt*16;
                unsigned a0 = shUT[r+gid  ][ks*8+t4  ];
                unsigned a1 = shUT[r+gid+8][ks*8+t4  ];
                unsigned a2 = shUT[r+gid  ][ks*8+t4+4];
                unsigned a3 = shUT[r+gid+8][ks*8+t4+4];
                #pragma unroll
                for (int nt = 0; nt < 4; nt++)
                    mma_tf32(d[mt][nt], a0, a1, a2, a3, bb[nt][0], bb[nt][1]);
            }
        }
        __syncthreads();
    }
    // agreement: elementwise dot of T tile with WgT, reduce to a[i][j]
    float p[2][2] = {};
    #pragma unroll
    for (int mt = 0; mt < 2; mt++){
        int r0 = wik*32 + mt*16 + gid, r1 = r0 + 8;
        #pragma unroll
        for (int nt = 0; nt < 4; nt++){
            int col = n0 + wju*32 + nt*8 + t4*2;
            float2 w0 = *(const float2*)&g_WgT[(size_t)r0*JUn + col];
            float2 w1 = *(const float2*)&g_WgT[(size_t)r1*JUn + col];
            p[mt][0] += d[mt][nt][0]*w0.x + d[mt][nt][1]*w0.y;
            p[mt][1] += d[mt][nt][2]*w1.x + d[mt][nt][3]*w1.y;
        }
    }
    #pragma unroll
    for (int mt = 0; mt < 2; mt++)
        #pragma unroll
        for (int h = 0; h < 2; h++){
            p[mt][h] += __shfl_xor_sync(0xffffffffu, p[mt][h], 1);
            p[mt][h] += __shfl_xor_sync(0xffffffffu, p[mt][h], 2);
        }
    if (t4 == 0){
        shAg[w][0*16 + 0 + gid] = p[0][0];
        shAg[w][0*16 + 8 + gid] = p[0][1];
        shAg[w][1*16 + 0 + gid] = p[1][0];
        shAg[w][1*16 + 8 + gid] = p[1][1];
    }
    __syncthreads();
    if (tid < 64){
        int i = tid >> 1, jg = tid & 1;
        float s = 0.f;
        #pragma unroll
        for (int k = 0; k < 4; k++) s += shAg[k*2 + jg][i];
        g_apart[((b*16 + msb)*8 + nblk)*64 + i*2 + jg] = s*(1.f/1024.f);
    }
}

// ---------------- aspect stage (hidden cancels; M collapses to 1) ----------------
__global__ __launch_bounds__(256) void k_aspect(const float* __restrict__ Wa,
                                                const float* __restrict__ Ws){
    __shared__ float g[CNn][CSn];
    __shared__ float cond[CNn][CSn];
    __shared__ float uh[CNn][NAn][CSn];
    __shared__ float b2[CNn][NAn];
    __shared__ float c2[CNn][NAn];
    __shared__ float s2[NAn][CSn];
    __shared__ float v2[NAn][CSn];
    __shared__ float facu[CSn];
    __shared__ float score[CNn];
    int b = blockIdx.x, tid = threadIdx.x;
    const float invN = 1.f/1024.f;
    for (int e = tid; e < JUn; e += 256){
        float t = 0.f;
        #pragma unroll
        for (int s = 0; s < 64; s++) t += g_gpart[((size_t)b*64 + s)*JUn + e];
        g[e>>5][e&31] = t*invN;
    }
    __syncthreads();
    if (tid == 0){
        float gw[CNn], mx = -1e30f;
        for (int i = 0; i < CNn; i++){
            float s = 0.f;
            for (int u = 0; u < CSn; u++) s += g[i][u]*Wa[u];
            gw[i] = s; mx = fmaxf(mx, s);
        }
        float sum = 0.f;
        for (int i = 0; i < CNn; i++){ gw[i] = expf(gw[i]-mx); sum += gw[i]; }
        float inv = 1.f/sum;
        for (int i = 0; i < CNn; i++) score[i] = gw[i]*inv;
    }
    __syncthreads();
    for (int e = tid; e < JUn; e += 256)
        cond[e>>5][e&31] = g[e>>5][e&31]*score[e>>5];
    if (tid < 256){ int i = tid >> 4, j = tid & 15; b2[i][j] = 0.f; }
    __syncthreads();
    for (int e = tid; e < CNn*NAn*CSn; e += 256){
        int i = e >> 9, j = (e >> 5) & 15, u = e & 31;
        float s = 0.f;
        const float* wrow = Ws + ((size_t)((i*NAn+j)*CSn+u))*CSn;
        #pragma unroll
        for (int k = 0; k < CSn; k++) s += wrow[k]*cond[i][k];
        uh[i][j][u] = s;
    }
    __syncthreads();
    for (int it = 0; it < 3; it++){
        if (tid < CNn){
            int i = tid;
            float mx = -1e30f;
            #pragma unroll
            for (int j = 0; j < NAn; j++) mx = fmaxf(mx, b2[i][j]);
            float sum = 0.f, r[NAn];
            #pragma unroll
            for (int j = 0; j < NAn; j++){ r[j] = expf(b2[i][j]-mx); sum += r[j]; }
            float inv = 1.f/sum;
            #pragma unroll
            for (int j = 0; j < NAn; j++) c2[i][j] = r[j]*inv;
        }
        __syncthreads();
        for (int e = tid; e < NAn*CSn; e += 256){
            int j = e >> 5, u = e & 31;
            float s = 0.f;
            #pragma unroll
            for (int i = 0; i < CNn; i++) s += c2[i][j]*uh[i][j][u];
            s2[j][u] = s;
        }
        __syncthreads();
        if (tid < CSn){
            int u = tid; float ms = 0.f;
            #pragma unroll
            for (int j = 0; j < NAn; j++) ms += s2[j][u]*s2[j][u];
            facu[u] = sqrtf(ms)/(1.f+ms);
        }
        __syncthreads();
        for (int e = tid; e < NAn*CSn; e += 256){
            int j = e >> 5, u = e & 31;
            v2[j][u] = s2[j][u]*facu[u];
        }
        __syncthreads();
        if (it < 2){
            if (tid < 256){
                int i = tid >> 4, j = tid & 15;
                float a = 0.f;
                #pragma unroll
                for (int u = 0; u < CSn; u++) a += uh[i][j][u]*v2[j][u];
                b2[i][j] += a;
            }
            __syncthreads();
        }
    }
    for (int e = tid; e < NAn*CSn; e += 256)
        g_va[b*NAn*CSn + e] = v2[e>>5][e&31];
}

// ---------------- broadcast final v to all S rows ----------------
__global__ __launch_bounds__(256) void k_broadcast(float* __restrict__ out){
    int idx = blockIdx.x*blockDim.x + threadIdx.x;
    if (idx < Bn*Sn*NAn*CSn){
        int b = idx >> 18;
        out[idx] = g_va[b*NAn*CSn + (idx & 511)];
    }
}

extern "C" void kernel_launch(void* const* d_in, const int* in_sizes, int n_in,
                              void* d_out, int out_size){
    (void)in_sizes; (void)n_in; (void)out_size;
    const float* ge = (const float*)d_in[0];
    // d_in[1] = hidden: cancels exactly in the softmax over capsules; never read.
    const float* Wp = (const float*)d_in[2];
    const float* bp = (const float*)d_in[3];
    const float* Wg = (const float*)d_in[4];
    const float* Wa = (const float*)d_in[5];
    const float* Ws = (const float*)d_in[6];
    float* out = (float*)d_out;

    k_permW<<<256, 256>>>(Wg);
    k_primary<<<dim3(8, 4, Bn), 256>>>(Wp, bp, ge);
    for (int t = 0; t < 3; t++){
        k_route<<<dim3(64, Bn), 256>>>(t);
        if (t < 2)
            k_T_agree<<<dim3(8, 16, Bn), 256>>>();
    }
    k_aspect<<<Bn, 256>>>(Wa, Ws);
    k_broadcast<<<(Bn*Sn*NAn*CSn + 255)/256, 256>>>(out);
}